// round 16
// baseline (speedup 1.0000x reference)
#include <cuda_runtime.h>
#include <math.h>

// ---------------------------------------------------------------------------
// Poincare transformer layer, B=4, S=1024, D=1024, H=16, HD=64, FF=4096.
// All expmap0/logmap0 chains reduce to row-wise scalar rescales:
//   logmap0(expmap0(t)) = t * atanh(min(tanh(||t||),MAXT)) / ||t||   (gel)
//   logmap0(point p)    = p * atanh(min(||p||,MAXT)) / ||p||         (glog)
//   expmap0(t)          = t * tanh(||t||) / ||t||                    (gexp)
// with ||.|| clamped below at EPS=1e-7 (matching the jax reference clips).
// ---------------------------------------------------------------------------

#define EPSF  1e-7f
#define MAXTF 0.99999f   // 1 - 1e-5

// ------------------------------ scratch (no allocs allowed) ----------------
__device__ float g_ada[4 * 6144];           // adaLN params per batch
__device__ float g_U  [4096 * 1024];        // tangent activations (reused)
__device__ float g_Y  [4096 * 1024];        // GEMM outputs (reused)
__device__ float g_Qt [64 * 1024 * 64];     // [B,H,S,HD] tangent q (pre-scaled by 1/8)
__device__ float g_Kt [64 * 1024 * 64];
__device__ float g_Vt [64 * 1024 * 64];
__device__ float g_Ot [64 * 1024 * 64];     // attn @ vt
__device__ float g_S  [64 * 1024 * 1024];   // scores / probs, 268MB
__device__ float g_Xn [4096 * 1024];        // x after attention mobius-add
__device__ float g_Y1 [4096 * 4096];        // FFN intermediate

// ------------------------------ small helpers ------------------------------
static __device__ __forceinline__ float dot4(float4 a, float4 b) {
    return a.x * b.x + a.y * b.y + a.z * b.z + a.w * b.w;
}

// block = 256 threads everywhere
static __device__ __forceinline__ float blk_sum(float v, float* red) {
#pragma unroll
    for (int o = 16; o > 0; o >>= 1) v += __shfl_xor_sync(0xffffffffu, v, o);
    int lane = threadIdx.x & 31, w = threadIdx.x >> 5;
    __syncthreads();
    if (lane == 0) red[w] = v;
    __syncthreads();
    float s = red[0];
#pragma unroll
    for (int i = 1; i < 8; i++) s += red[i];
    return s;
}

static __device__ __forceinline__ float blk_max(float v, float* red) {
#pragma unroll
    for (int o = 16; o > 0; o >>= 1) v = fmaxf(v, __shfl_xor_sync(0xffffffffu, v, o));
    int lane = threadIdx.x & 31, w = threadIdx.x >> 5;
    __syncthreads();
    if (lane == 0) red[w] = v;
    __syncthreads();
    float s = red[0];
#pragma unroll
    for (int i = 1; i < 8; i++) s = fmaxf(s, red[i]);
    return s;
}

static __device__ __forceinline__ float grp16_sum(float v) {
#pragma unroll
    for (int o = 8; o > 0; o >>= 1) v += __shfl_xor_sync(0xffffffffu, v, o);
    return v;
}

// scale factors, all take SQUARED norm
static __device__ __forceinline__ float gel_scale(float n2) {   // logmap0(expmap0(.))
    float n = fmaxf(sqrtf(n2), EPSF);
    return atanhf(fminf(tanhf(n), MAXTF)) / n;
}
static __device__ __forceinline__ float glog_scale(float n2) {  // logmap0(point)
    float n = fmaxf(sqrtf(n2), EPSF);
    return atanhf(fminf(n, MAXTF)) / n;
}
static __device__ __forceinline__ float gexp_scale(float n2) {  // expmap0(tangent)
    float n = fmaxf(sqrtf(n2), EPSF);
    return tanhf(n) / n;
}

// ------------------------------ ada GEMM (tiny) -----------------------------
__global__ void k_ada(const float* __restrict__ t_emb,
                      const float* __restrict__ w,
                      const float* __restrict__ bias) {
    __shared__ float ts[1024];
    int b = blockIdx.y;
    for (int i = threadIdx.x; i < 1024; i += 256) ts[i] = t_emb[b * 1024 + i];
    __syncthreads();
    int c = blockIdx.x * 256 + threadIdx.x;   // 0..6143
    float acc = bias[c];
    for (int k = 0; k < 1024; k++) acc += ts[k] * w[(size_t)k * 6144 + c];
    g_ada[b * 6144 + c] = acc;
}

// ------------------------------ pre-attention rowwise ----------------------
// U = gel( LN(logmap0(x)) * (1+sc_msa) + sh_msa )
__global__ void k_pre(const float* __restrict__ x, float* __restrict__ U) {
    __shared__ float red[32];
    int row = blockIdx.x;
    int b = row >> 10;
    int tid = threadIdx.x;
    float4 xv = ((const float4*)(x + (size_t)row * 1024))[tid];
    float sl = glog_scale(blk_sum(dot4(xv, xv), red));
    float t0 = xv.x * sl, t1 = xv.y * sl, t2 = xv.z * sl, t3 = xv.w * sl;
    float m = blk_sum(t0 + t1 + t2 + t3, red) * (1.0f / 1024.0f);
    float d0 = t0 - m, d1 = t1 - m, d2 = t2 - m, d3 = t3 - m;
    float var = blk_sum(d0 * d0 + d1 * d1 + d2 * d2 + d3 * d3, red) * (1.0f / 1024.0f);
    float inv = rsqrtf(var + 1e-6f);
    const float* ab = g_ada + b * 6144;
    float4 sh = ((const float4*)(ab))[tid];          // sh_msa
    float4 sc = ((const float4*)(ab + 1024))[tid];   // sc_msa
    float m0 = d0 * inv * (1.0f + sc.x) + sh.x;
    float m1 = d1 * inv * (1.0f + sc.y) + sh.y;
    float m2 = d2 * inv * (1.0f + sc.z) + sh.z;
    float m3 = d3 * inv * (1.0f + sc.w) + sh.w;
    float s = gel_scale(blk_sum(m0 * m0 + m1 * m1 + m2 * m2 + m3 * m3, red));
    ((float4*)(U + (size_t)row * 1024))[tid] = make_float4(m0 * s, m1 * s, m2 * s, m3 * s);
}

// ------------------------------ main SGEMM (NN, fp32, bias) -----------------
// C[M,N] = A[M,K] @ B[K,N] + bias.  128x128x8 tiles, 8x8 per thread.
__global__ void __launch_bounds__(256, 2)
sgemm_nn(const float* __restrict__ A, const float* __restrict__ B,
         const float* __restrict__ bias, float* __restrict__ C,
         int M, int N, int K) {
    __shared__ float As[8][128];
    __shared__ float Bs[8][128];
    int tid = threadIdx.x;
    int arow = tid >> 1, acol = (tid & 1) << 2;
    int brow = tid >> 5, bcol = (tid & 31) << 2;
    const float* Ap = A + (size_t)(blockIdx.y * 128 + arow) * K + acol;
    const float* Bp = B + (size_t)brow * N + blockIdx.x * 128 + bcol;
    int tx = tid & 15, ty = tid >> 4;
    float acc[8][8];
#pragma unroll
    for (int i = 0; i < 8; i++)
#pragma unroll
        for (int j = 0; j < 8; j++) acc[i][j] = 0.0f;

    for (int k0 = 0; k0 < K; k0 += 8) {
        float4 av = *(const float4*)(Ap + k0);
        float4 bv = *(const float4*)(Bp + (size_t)k0 * N);
        As[acol + 0][arow] = av.x;
        As[acol + 1][arow] = av.y;
        As[acol + 2][arow] = av.z;
        As[acol + 3][arow] = av.w;
        *(float4*)&Bs[brow][bcol] = bv;
        __syncthreads();
#pragma unroll
        for (int k = 0; k < 8; k++) {
            float4 a0 = *(const float4*)&As[k][ty * 8];
            float4 a1 = *(const float4*)&As[k][ty * 8 + 4];
            float4 b0 = *(const float4*)&Bs[k][tx * 8];
            float4 b1 = *(const float4*)&Bs[k][tx * 8 + 4];
            float a[8] = {a0.x, a0.y, a0.z, a0.w, a1.x, a1.y, a1.z, a1.w};
            float bb[8] = {b0.x, b0.y, b0.z, b0.w, b1.x, b1.y, b1.z, b1.w};
#pragma unroll
            for (int i = 0; i < 8; i++)
#pragma unroll
                for (int j = 0; j < 8; j++) acc[i][j] += a[i] * bb[j];
        }
        __syncthreads();
    }
    int crow = blockIdx.y * 128 + ty * 8;
    int ccol = blockIdx.x * 128 + tx * 8;
    float bi[8];
#pragma unroll
    for (int j = 0; j < 8; j++) bi[j] = bias[ccol + j];
#pragma unroll
    for (int i = 0; i < 8; i++) {
        float4 o0 = make_float4(acc[i][0] + bi[0], acc[i][1] + bi[1],
                                acc[i][2] + bi[2], acc[i][3] + bi[3]);
        float4 o1 = make_float4(acc[i][4] + bi[4], acc[i][5] + bi[5],
                                acc[i][6] + bi[6], acc[i][7] + bi[7]);
        *(float4*)(C + (size_t)(crow + i) * N + ccol) = o0;
        *(float4*)(C + (size_t)(crow + i) * N + ccol + 4) = o1;
    }
}

// ------------------------------ head split ---------------------------------
// Out[b,h,s,:] = Y[b,s,:].head(h) * gel(full)*rscale , then * gel(head)*extra
__global__ void k_split(const float* __restrict__ Y, float* __restrict__ Out,
                        float rscale, float extrascale) {
    __shared__ float red[32];
    int row = blockIdx.x;
    int b = row >> 10, s = row & 1023;
    int tid = threadIdx.x;
    float4 yv = ((const float4*)(Y + (size_t)row * 1024))[tid];
    float sf = gel_scale(blk_sum(dot4(yv, yv), red)) * rscale;
    float t0 = yv.x * sf, t1 = yv.y * sf, t2 = yv.z * sf, t3 = yv.w * sf;
    float h2 = grp16_sum(t0 * t0 + t1 * t1 + t2 * t2 + t3 * t3);
    float hs = gel_scale(h2) * extrascale;
    int h = tid >> 4, dd = (tid & 15) << 2;
    ((float4*)(Out + (((size_t)(b * 16 + h)) * 1024 + s) * 64 + dd))[0] =
        make_float4(t0 * hs, t1 * hs, t2 * hs, t3 * hs);
}

// ------------------------------ scores: batched NT GEMM (K=64) --------------
__global__ void __launch_bounds__(256, 2)
k_scores(const float* __restrict__ Q, const float* __restrict__ Kt) {
    __shared__ float Qs[8][128];
    __shared__ float Ks[8][128];
    int bh = blockIdx.z;
    const float* Qb = Q + (size_t)bh * 1024 * 64;
    const float* Kb = Kt + (size_t)bh * 1024 * 64;
    int tid = threadIdx.x;
    int lr = tid >> 1, lc = (tid & 1) << 2;
    const float* Ap = Qb + (size_t)(blockIdx.y * 128 + lr) * 64 + lc;
    const float* Bp = Kb + (size_t)(blockIdx.x * 128 + lr) * 64 + lc;
    int tx = tid & 15, ty = tid >> 4;
    float acc[8][8];
#pragma unroll
    for (int i = 0; i < 8; i++)
#pragma unroll
        for (int j = 0; j < 8; j++) acc[i][j] = 0.0f;

#pragma unroll
    for (int k0 = 0; k0 < 64; k0 += 8) {
        float4 av = *(const float4*)(Ap + k0);
        float4 bv = *(const float4*)(Bp + k0);
        Qs[lc + 0][lr] = av.x; Qs[lc + 1][lr] = av.y;
        Qs[lc + 2][lr] = av.z; Qs[lc + 3][lr] = av.w;
        Ks[lc + 0][lr] = bv.x; Ks[lc + 1][lr] = bv.y;
        Ks[lc + 2][lr] = bv.z; Ks[lc + 3][lr] = bv.w;
        __syncthreads();
#pragma unroll
        for (int k = 0; k < 8; k++) {
            float4 a0 = *(const float4*)&Qs[k][ty * 8];
            float4 a1 = *(const float4*)&Qs[k][ty * 8 + 4];
            float4 b0 = *(const float4*)&Ks[k][tx * 8];
            float4 b1 = *(const float4*)&Ks[k][tx * 8 + 4];
            float a[8] = {a0.x, a0.y, a0.z, a0.w, a1.x, a1.y, a1.z, a1.w};
            float bb[8] = {b0.x, b0.y, b0.z, b0.w, b1.x, b1.y, b1.z, b1.w};
#pragma unroll
            for (int i = 0; i < 8; i++)
#pragma unroll
                for (int j = 0; j < 8; j++) acc[i][j] += a[i] * bb[j];
        }
        __syncthreads();
    }
    float* Cb = g_S + (size_t)bh * 1024 * 1024;
    int crow = blockIdx.y * 128 + ty * 8;
    int ccol = blockIdx.x * 128 + tx * 8;
#pragma unroll
    for (int i = 0; i < 8; i++) {
        *(float4*)(Cb + (size_t)(crow + i) * 1024 + ccol) =
            make_float4(acc[i][0], acc[i][1], acc[i][2], acc[i][3]);
        *(float4*)(Cb + (size_t)(crow + i) * 1024 + ccol + 4) =
            make_float4(acc[i][4], acc[i][5], acc[i][6], acc[i][7]);
    }
}

// ------------------------------ softmax rows --------------------------------
__global__ void k_softmax() {
    __shared__ float red[32];
    float* p = g_S + (size_t)blockIdx.x * 1024;
    int tid = threadIdx.x;
    float4 v = ((float4*)p)[tid];
    float mx = blk_max(fmaxf(fmaxf(v.x, v.y), fmaxf(v.z, v.w)), red);
    v.x = expf(v.x - mx); v.y = expf(v.y - mx);
    v.z = expf(v.z - mx); v.w = expf(v.w - mx);
    float s = blk_sum(v.x + v.y + v.z + v.w, red);
    float inv = 1.0f / s;
    v.x *= inv; v.y *= inv; v.z *= inv; v.w *= inv;
    ((float4*)p)[tid] = v;
}

// ------------------------------ attn @ V : batched NN (N=64) ----------------
__global__ void __launch_bounds__(256, 2)
k_av(const float* __restrict__ V, float* __restrict__ O) {
    __shared__ float Ps[16][128];
    __shared__ float Vs[16][64];
    int bh = blockIdx.z;
    const float* Pb = g_S + (size_t)bh * 1024 * 1024;
    const float* Vb = V + (size_t)bh * 1024 * 64;
    int tid = threadIdx.x;
    int pr = tid >> 1, pc = (tid & 1) << 3;
    int vr = tid >> 4, vc = (tid & 15) << 2;
    int tx = tid & 15, ty = tid >> 4;
    float acc[8][4];
#pragma unroll
    for (int i = 0; i < 8; i++)
#pragma unroll
        for (int j = 0; j < 4; j++) acc[i][j] = 0.0f;

    const float* Prow = Pb + (size_t)(blockIdx.x * 128 + pr) * 1024 + pc;
    for (int k0 = 0; k0 < 1024; k0 += 16) {
        float4 p0 = *(const float4*)(Prow + k0);
        float4 p1 = *(const float4*)(Prow + k0 + 4);
        float4 vv = *(const float4*)(Vb + (size_t)(k0 + vr) * 64 + vc);
        Ps[pc + 0][pr] = p0.x; Ps[pc + 1][pr] = p0.y;
        Ps[pc + 2][pr] = p0.z; Ps[pc + 3][pr] = p0.w;
        Ps[pc + 4][pr] = p1.x; Ps[pc + 5][pr] = p1.y;
        Ps[pc + 6][pr] = p1.z; Ps[pc + 7][pr] = p1.w;
        *(float4*)&Vs[vr][vc] = vv;
        __syncthreads();
#pragma unroll
        for (int k = 0; k < 16; k++) {
            float4 a0 = *(const float4*)&Ps[k][ty * 8];
            float4 a1 = *(const float4*)&Ps[k][ty * 8 + 4];
            float4 b = *(const float4*)&Vs[k][tx * 4];
            float a[8] = {a0.x, a0.y, a0.z, a0.w, a1.x, a1.y, a1.z, a1.w};
            float bb[4] = {b.x, b.y, b.z, b.w};
#pragma unroll
            for (int i = 0; i < 8; i++)
#pragma unroll
                for (int j = 0; j < 4; j++) acc[i][j] += a[i] * bb[j];
        }
        __syncthreads();
    }
    int crow = blockIdx.x * 128 + ty * 8;
    int ccol = tx * 4;
#pragma unroll
    for (int i = 0; i < 8; i++) {
        *(float4*)(O + (size_t)bh * 1024 * 64 + (size_t)(crow + i) * 64 + ccol) =
            make_float4(acc[i][0], acc[i][1], acc[i][2], acc[i][3]);
    }
}

// ------------------------------ merge heads --------------------------------
// U = gel(full) * concat_h( Ot_h * gel(head) * invr )
__global__ void k_merge(const float* __restrict__ Ot, float* __restrict__ U, float invr) {
    __shared__ float red[32];
    int row = blockIdx.x;
    int b = row >> 10, s = row & 1023;
    int tid = threadIdx.x;
    int h = tid >> 4, dd = (tid & 15) << 2;
    float4 v = ((const float4*)(Ot + (((size_t)(b * 16 + h)) * 1024 + s) * 64 + dd))[0];
    float hs = gel_scale(grp16_sum(dot4(v, v))) * invr;
    float t0 = v.x * hs, t1 = v.y * hs, t2 = v.z * hs, t3 = v.w * hs;
    float fs = gel_scale(blk_sum(t0 * t0 + t1 * t1 + t2 * t2 + t3 * t3, red));
    ((float4*)(U + (size_t)row * 1024))[tid] =
        make_float4(t0 * fs, t1 * fs, t2 * fs, t3 * fs);
}

// ------------------------------ post-attn: mobius add + FFN pre -------------
__global__ void k_post_attn(const float* __restrict__ x, const float* __restrict__ Yo,
                            float* __restrict__ Xn, float* __restrict__ U2) {
    __shared__ float red[32];
    int row = blockIdx.x;
    int b = row >> 10;
    int tid = threadIdx.x;
    const float* ab = g_ada + b * 6144;
    float4 yv = ((const float4*)(Yo + (size_t)row * 1024))[tid];
    float sl = gel_scale(blk_sum(dot4(yv, yv), red));        // logmap0(expmap0(y_o))
    float4 gm = ((const float4*)(ab + 2048))[tid];           // g_msa
    float a0 = gm.x * yv.x * sl, a1 = gm.y * yv.y * sl;
    float a2 = gm.z * yv.z * sl, a3 = gm.w * yv.w * sl;
    float na2 = blk_sum(a0 * a0 + a1 * a1 + a2 * a2 + a3 * a3, red);
    float se = gexp_scale(na2);
    float y0 = a0 * se, y1 = a1 * se, y2c = a2 * se, y3 = a3 * se;
    float4 xv = ((const float4*)(x + (size_t)row * 1024))[tid];
    float x2 = blk_sum(dot4(xv, xv), red);
    float y2 = blk_sum(y0 * y0 + y1 * y1 + y2c * y2c + y3 * y3, red);
    float xy = blk_sum(xv.x * y0 + xv.y * y1 + xv.z * y2c + xv.w * y3, red);
    float den = fmaxf(1.0f + 2.0f * xy + x2 * y2, EPSF);
    float cx = (1.0f + 2.0f * xy + y2) / den;
    float cy = (1.0f - x2) / den;
    float n0 = cx * xv.x + cy * y0, n1 = cx * xv.y + cy * y1;
    float n2 = cx * xv.z + cy * y2c, n3 = cx * xv.w + cy * y3;
    ((float4*)(Xn + (size_t)row * 1024))[tid] = make_float4(n0, n1, n2, n3);
    // FFN pre: gel( LN(logmap0(xn)) * (1+sc_mlp) + sh_mlp )
    float ls = glog_scale(blk_sum(n0 * n0 + n1 * n1 + n2 * n2 + n3 * n3, red));
    float t0 = n0 * ls, t1 = n1 * ls, t2 = n2 * ls, t3 = n3 * ls;
    float m = blk_sum(t0 + t1 + t2 + t3, red) * (1.0f / 1024.0f);
    float d0 = t0 - m, d1 = t1 - m, d2 = t2 - m, d3 = t3 - m;
    float var = blk_sum(d0 * d0 + d1 * d1 + d2 * d2 + d3 * d3, red) * (1.0f / 1024.0f);
    float inv = rsqrtf(var + 1e-6f);
    float4 shp = ((const float4*)(ab + 3072))[tid];   // sh_mlp
    float4 scp = ((const float4*)(ab + 4096))[tid];   // sc_mlp
    float m0 = d0 * inv * (1.0f + scp.x) + shp.x;
    float m1 = d1 * inv * (1.0f + scp.y) + shp.y;
    float m2 = d2 * inv * (1.0f + scp.z) + shp.z;
    float m3 = d3 * inv * (1.0f + scp.w) + shp.w;
    float gs = gel_scale(blk_sum(m0 * m0 + m1 * m1 + m2 * m2 + m3 * m3, red));
    ((float4*)(U2 + (size_t)row * 1024))[tid] =
        make_float4(m0 * gs, m1 * gs, m2 * gs, m3 * gs);
}

// ------------------------------ FF renorm (rows of 4096) --------------------
__global__ void k_renorm_ff(float* __restrict__ Y1) {
    __shared__ float red[32];
    int row = blockIdx.x;
    int tid = threadIdx.x;
    float4* p = (float4*)(Y1 + (size_t)row * 4096);
    float4 v0 = p[tid], v1 = p[tid + 256], v2 = p[tid + 512], v3 = p[tid + 768];
    float s2 = dot4(v0, v0) + dot4(v1, v1) + dot4(v2, v2) + dot4(v3, v3);
    float s = gel_scale(blk_sum(s2, red));
    v0.x *= s; v0.y *= s; v0.z *= s; v0.w *= s;
    v1.x *= s; v1.y *= s; v1.z *= s; v1.w *= s;
    v2.x *= s; v2.y *= s; v2.z *= s; v2.w *= s;
    v3.x *= s; v3.y *= s; v3.z *= s; v3.w *= s;
    p[tid] = v0; p[tid + 256] = v1; p[tid + 512] = v2; p[tid + 768] = v3;
}

// ------------------------------ final: FFN mobius add -----------------------
__global__ void k_final(const float* __restrict__ Xn, const float* __restrict__ Y2,
                        float* __restrict__ out) {
    __shared__ float red[32];
    int row = blockIdx.x;
    int b = row >> 10;
    int tid = threadIdx.x;
    const float* ab = g_ada + b * 6144;
    float4 yv = ((const float4*)(Y2 + (size_t)row * 1024))[tid];
    float sl = gel_scale(blk_sum(dot4(yv, yv), red));
    float4 gm = ((const float4*)(ab + 5120))[tid];   // g_mlp
    float a0 = gm.x * yv.x * sl, a1 = gm.y * yv.y * sl;
    float a2 = gm.z * yv.z * sl, a3 = gm.w * yv.w * sl;
    float na2 = blk_sum(a0 * a0 + a1 * a1 + a2 * a2 + a3 * a3, red);
    float se = gexp_scale(na2);
    float y0 = a0 * se, y1 = a1 * se, y2c = a2 * se, y3 = a3 * se;
    float4 xv = ((const float4*)(Xn + (size_t)row * 1024))[tid];
    float x2 = blk_sum(dot4(xv, xv), red);
    float y2 = blk_sum(y0 * y0 + y1 * y1 + y2c * y2c + y3 * y3, red);
    float xy = blk_sum(xv.x * y0 + xv.y * y1 + xv.z * y2c + xv.w * y3, red);
    float den = fmaxf(1.0f + 2.0f * xy + x2 * y2, EPSF);
    float cx = (1.0f + 2.0f * xy + y2) / den;
    float cy = (1.0f - x2) / den;
    ((float4*)(out + (size_t)row * 1024))[tid] =
        make_float4(cx * xv.x + cy * y0, cx * xv.y + cy * y1,
                    cx * xv.z + cy * y2c, cx * xv.w + cy * y3);
}

// ------------------------------ launcher -----------------------------------
extern "C" void kernel_launch(void* const* d_in, const int* in_sizes, int n_in,
                              void* d_out, int out_size) {
    const float* x     = (const float*)d_in[0];
    const float* t_emb = (const float*)d_in[1];
    const float* w_q   = (const float*)d_in[2];
    const float* b_q   = (const float*)d_in[3];
    const float* w_k   = (const float*)d_in[4];
    const float* b_k   = (const float*)d_in[5];
    const float* w_v   = (const float*)d_in[6];
    const float* b_v   = (const float*)d_in[7];
    const float* w_o   = (const float*)d_in[8];
    const float* b_o   = (const float*)d_in[9];
    const float* w_f1  = (const float*)d_in[10];
    const float* b_f1  = (const float*)d_in[11];
    const float* w_f2  = (const float*)d_in[12];
    const float* b_f2  = (const float*)d_in[13];
    const float* w_ada = (const float*)d_in[14];
    const float* b_ada = (const float*)d_in[15];
    float* out = (float*)d_out;

    // beta(D/2, 1/2) ratios, computed in double exactly like the reference
    double bn = exp(lgamma(512.0) + lgamma(0.5) - lgamma(512.5));
    double bh = exp(lgamma(32.0) + lgamma(0.5) - lgamma(32.5));
    float rscale = (float)(bh / bn);   // BETA_H / BETA_N
    float invr   = (float)(bn / bh);   // BETA_N / BETA_H

    float *pU, *pY, *pQt, *pKt, *pVt, *pOt, *pXn, *pY1;
    cudaGetSymbolAddress((void**)&pU,  g_U);
    cudaGetSymbolAddress((void**)&pY,  g_Y);
    cudaGetSymbolAddress((void**)&pQt, g_Qt);
    cudaGetSymbolAddress((void**)&pKt, g_Kt);
    cudaGetSymbolAddress((void**)&pVt, g_Vt);
    cudaGetSymbolAddress((void**)&pOt, g_Ot);
    cudaGetSymbolAddress((void**)&pXn, g_Xn);
    cudaGetSymbolAddress((void**)&pY1, g_Y1);

    // ada params
    k_ada<<<dim3(24, 4), 256>>>(t_emb, w_ada, b_ada);
    // attention pre
    k_pre<<<4096, 256>>>(x, pU);
    // Q, K, V projections + head split (q pre-scaled by 1/sqrt(HD)=0.125)
    sgemm_nn<<<dim3(8, 32), 256>>>(pU, w_q, b_q, pY, 4096, 1024, 1024);
    k_split<<<4096, 256>>>(pY, pQt, rscale, 0.125f);
    sgemm_nn<<<dim3(8, 32), 256>>>(pU, w_k, b_k, pY, 4096, 1024, 1024);
    k_split<<<4096, 256>>>(pY, pKt, rscale, 1.0f);
    sgemm_nn<<<dim3(8, 32), 256>>>(pU, w_v, b_v, pY, 4096, 1024, 1024);
    k_split<<<4096, 256>>>(pY, pVt, rscale, 1.0f);
    // attention
    k_scores<<<dim3(8, 8, 64), 256>>>(pQt, pKt);
    k_softmax<<<65536, 256>>>();
    k_av<<<dim3(8, 1, 64), 256>>>(pVt, pOt);
    // merge heads + O projection
    k_merge<<<4096, 256>>>(pOt, pU, invr);
    sgemm_nn<<<dim3(8, 32), 256>>>(pU, w_o, b_o, pY, 4096, 1024, 1024);
    // mobius residual + FFN pre
    k_post_attn<<<4096, 256>>>(x, pY, pXn, pU);
    // FFN
    sgemm_nn<<<dim3(32, 32), 256>>>(pU, w_f1, b_f1, pY1, 4096, 4096, 1024);
    k_renorm_ff<<<4096, 256>>>(pY1);
    sgemm_nn<<<dim3(8, 32), 256>>>(pY1, w_f2, b_f2, pY, 4096, 1024, 4096);
    // final mobius residual
    k_final<<<4096, 256>>>(pXn, pY, out);
}

// round 17
// speedup vs baseline: 1.0002x; 1.0002x over previous
#include <cuda_runtime.h>
#include <math.h>

// ---------------------------------------------------------------------------
// Poincare transformer layer, B=4, S=1024, D=1024, H=16, HD=64, FF=4096.
// All expmap0/logmap0 chains reduce to row-wise scalar rescales:
//   logmap0(expmap0(t)) = t * atanh(min(tanh(||t||),MAXT)) / ||t||   (gel)
//   logmap0(point p)    = p * atanh(min(||p||,MAXT)) / ||p||         (glog)
//   expmap0(t)          = t * tanh(||t||) / ||t||                    (gexp)
// with ||.|| clamped below at EPS=1e-7 (matching the jax reference clips).
// ---------------------------------------------------------------------------

#define EPSF  1e-7f
#define MAXTF 0.99999f   // 1 - 1e-5

// ------------------------------ scratch (no allocs allowed) ----------------
__device__ float g_ada[4 * 6144];           // adaLN params per batch
__device__ float g_U  [4096 * 1024];        // tangent activations (reused)
__device__ float g_Y  [4096 * 1024];        // GEMM outputs (reused)
__device__ float g_Qt [64 * 1024 * 64];     // [B,H,S,HD] tangent q (pre-scaled by 1/8)
__device__ float g_Kt [64 * 1024 * 64];
__device__ float g_Vt [64 * 1024 * 64];
__device__ float g_Ot [64 * 1024 * 64];     // attn @ vt
__device__ float g_S  [64 * 1024 * 1024];   // scores / probs, 268MB
__device__ float g_Xn [4096 * 1024];        // x after attention mobius-add
__device__ float g_Y1 [4096 * 4096];        // FFN intermediate

// ------------------------------ small helpers ------------------------------
static __device__ __forceinline__ float dot4(float4 a, float4 b) {
    return a.x * b.x + a.y * b.y + a.z * b.z + a.w * b.w;
}

// block = 256 threads everywhere
static __device__ __forceinline__ float blk_sum(float v, float* red) {
#pragma unroll
    for (int o = 16; o > 0; o >>= 1) v += __shfl_xor_sync(0xffffffffu, v, o);
    int lane = threadIdx.x & 31, w = threadIdx.x >> 5;
    __syncthreads();
    if (lane == 0) red[w] = v;
    __syncthreads();
    float s = red[0];
#pragma unroll
    for (int i = 1; i < 8; i++) s += red[i];
    return s;
}

static __device__ __forceinline__ float blk_max(float v, float* red) {
#pragma unroll
    for (int o = 16; o > 0; o >>= 1) v = fmaxf(v, __shfl_xor_sync(0xffffffffu, v, o));
    int lane = threadIdx.x & 31, w = threadIdx.x >> 5;
    __syncthreads();
    if (lane == 0) red[w] = v;
    __syncthreads();
    float s = red[0];
#pragma unroll
    for (int i = 1; i < 8; i++) s = fmaxf(s, red[i]);
    return s;
}

static __device__ __forceinline__ float grp16_sum(float v) {
#pragma unroll
    for (int o = 8; o > 0; o >>= 1) v += __shfl_xor_sync(0xffffffffu, v, o);
    return v;
}

// scale factors, all take SQUARED norm
static __device__ __forceinline__ float gel_scale(float n2) {   // logmap0(expmap0(.))
    float n = fmaxf(sqrtf(n2), EPSF);
    return atanhf(fminf(tanhf(n), MAXTF)) / n;
}
static __device__ __forceinline__ float glog_scale(float n2) {  // logmap0(point)
    float n = fmaxf(sqrtf(n2), EPSF);
    return atanhf(fminf(n, MAXTF)) / n;
}
static __device__ __forceinline__ float gexp_scale(float n2) {  // expmap0(tangent)
    float n = fmaxf(sqrtf(n2), EPSF);
    return tanhf(n) / n;
}

// ------------------------------ ada GEMM (tiny) -----------------------------
__global__ void k_ada(const float* __restrict__ t_emb,
                      const float* __restrict__ w,
                      const float* __restrict__ bias) {
    __shared__ float ts[1024];
    int b = blockIdx.y;
    for (int i = threadIdx.x; i < 1024; i += 256) ts[i] = t_emb[b * 1024 + i];
    __syncthreads();
    int c = blockIdx.x * 256 + threadIdx.x;   // 0..6143
    float acc = bias[c];
    for (int k = 0; k < 1024; k++) acc += ts[k] * w[(size_t)k * 6144 + c];
    g_ada[b * 6144 + c] = acc;
}

// ------------------------------ pre-attention rowwise ----------------------
// U = gel( LN(logmap0(x)) * (1+sc_msa) + sh_msa )
__global__ void k_pre(const float* __restrict__ x, float* __restrict__ U) {
    __shared__ float red[32];
    int row = blockIdx.x;
    int b = row >> 10;
    int tid = threadIdx.x;
    float4 xv = ((const float4*)(x + (size_t)row * 1024))[tid];
    float sl = glog_scale(blk_sum(dot4(xv, xv), red));
    float t0 = xv.x * sl, t1 = xv.y * sl, t2 = xv.z * sl, t3 = xv.w * sl;
    float m = blk_sum(t0 + t1 + t2 + t3, red) * (1.0f / 1024.0f);
    float d0 = t0 - m, d1 = t1 - m, d2 = t2 - m, d3 = t3 - m;
    float var = blk_sum(d0 * d0 + d1 * d1 + d2 * d2 + d3 * d3, red) * (1.0f / 1024.0f);
    float inv = rsqrtf(var + 1e-6f);
    const float* ab = g_ada + b * 6144;
    float4 sh = ((const float4*)(ab))[tid];          // sh_msa
    float4 sc = ((const float4*)(ab + 1024))[tid];   // sc_msa
    float m0 = d0 * inv * (1.0f + sc.x) + sh.x;
    float m1 = d1 * inv * (1.0f + sc.y) + sh.y;
    float m2 = d2 * inv * (1.0f + sc.z) + sh.z;
    float m3 = d3 * inv * (1.0f + sc.w) + sh.w;
    float s = gel_scale(blk_sum(m0 * m0 + m1 * m1 + m2 * m2 + m3 * m3, red));
    ((float4*)(U + (size_t)row * 1024))[tid] = make_float4(m0 * s, m1 * s, m2 * s, m3 * s);
}

// ------------------------------ main SGEMM (NN, fp32, bias) -----------------
// C[M,N] = A[M,K] @ B[K,N] + bias.  128x128x8 tiles, 8x8 per thread.
__global__ void __launch_bounds__(256, 2)
sgemm_nn(const float* __restrict__ A, const float* __restrict__ B,
         const float* __restrict__ bias, float* __restrict__ C,
         int M, int N, int K) {
    __shared__ float As[8][128];
    __shared__ float Bs[8][128];
    int tid = threadIdx.x;
    int arow = tid >> 1, acol = (tid & 1) << 2;
    int brow = tid >> 5, bcol = (tid & 31) << 2;
    const float* Ap = A + (size_t)(blockIdx.y * 128 + arow) * K + acol;
    const float* Bp = B + (size_t)brow * N + blockIdx.x * 128 + bcol;
    int tx = tid & 15, ty = tid >> 4;
    float acc[8][8];
#pragma unroll
    for (int i = 0; i < 8; i++)
#pragma unroll
        for (int j = 0; j < 8; j++) acc[i][j] = 0.0f;

    for (int k0 = 0; k0 < K; k0 += 8) {
        float4 av = *(const float4*)(Ap + k0);
        float4 bv = *(const float4*)(Bp + (size_t)k0 * N);
        As[acol + 0][arow] = av.x;
        As[acol + 1][arow] = av.y;
        As[acol + 2][arow] = av.z;
        As[acol + 3][arow] = av.w;
        *(float4*)&Bs[brow][bcol] = bv;
        __syncthreads();
#pragma unroll
        for (int k = 0; k < 8; k++) {
            float4 a0 = *(const float4*)&As[k][ty * 8];
            float4 a1 = *(const float4*)&As[k][ty * 8 + 4];
            float4 b0 = *(const float4*)&Bs[k][tx * 8];
            float4 b1 = *(const float4*)&Bs[k][tx * 8 + 4];
            float a[8] = {a0.x, a0.y, a0.z, a0.w, a1.x, a1.y, a1.z, a1.w};
            float bb[8] = {b0.x, b0.y, b0.z, b0.w, b1.x, b1.y, b1.z, b1.w};
#pragma unroll
            for (int i = 0; i < 8; i++)
#pragma unroll
                for (int j = 0; j < 8; j++) acc[i][j] += a[i] * bb[j];
        }
        __syncthreads();
    }
    int crow = blockIdx.y * 128 + ty * 8;
    int ccol = blockIdx.x * 128 + tx * 8;
    float bi[8];
#pragma unroll
    for (int j = 0; j < 8; j++) bi[j] = bias[ccol + j];
#pragma unroll
    for (int i = 0; i < 8; i++) {
        float4 o0 = make_float4(acc[i][0] + bi[0], acc[i][1] + bi[1],
                                acc[i][2] + bi[2], acc[i][3] + bi[3]);
        float4 o1 = make_float4(acc[i][4] + bi[4], acc[i][5] + bi[5],
                                acc[i][6] + bi[6], acc[i][7] + bi[7]);
        *(float4*)(C + (size_t)(crow + i) * N + ccol) = o0;
        *(float4*)(C + (size_t)(crow + i) * N + ccol + 4) = o1;
    }
}

// ------------------------------ head split ---------------------------------
// Out[b,h,s,:] = Y[b,s,:].head(h) * gel(full)*rscale , then * gel(head)*extra
__global__ void k_split(const float* __restrict__ Y, float* __restrict__ Out,
                        float rscale, float extrascale) {
    __shared__ float red[32];
    int row = blockIdx.x;
    int b = row >> 10, s = row & 1023;
    int tid = threadIdx.x;
    float4 yv = ((const float4*)(Y + (size_t)row * 1024))[tid];
    float sf = gel_scale(blk_sum(dot4(yv, yv), red)) * rscale;
    float t0 = yv.x * sf, t1 = yv.y * sf, t2 = yv.z * sf, t3 = yv.w * sf;
    float h2 = grp16_sum(t0 * t0 + t1 * t1 + t2 * t2 + t3 * t3);
    float hs = gel_scale(h2) * extrascale;
    int h = tid >> 4, dd = (tid & 15) << 2;
    ((float4*)(Out + (((size_t)(b * 16 + h)) * 1024 + s) * 64 + dd))[0] =
        make_float4(t0 * hs, t1 * hs, t2 * hs, t3 * hs);
}

// ------------------------------ scores: batched NT GEMM (K=64) --------------
__global__ void __launch_bounds__(256, 2)
k_scores(const float* __restrict__ Q, const float* __restrict__ Kt) {
    __shared__ float Qs[8][128];
    __shared__ float Ks[8][128];
    int bh = blockIdx.z;
    const float* Qb = Q + (size_t)bh * 1024 * 64;
    const float* Kb = Kt + (size_t)bh * 1024 * 64;
    int tid = threadIdx.x;
    int lr = tid >> 1, lc = (tid & 1) << 2;
    const float* Ap = Qb + (size_t)(blockIdx.y * 128 + lr) * 64 + lc;
    const float* Bp = Kb + (size_t)(blockIdx.x * 128 + lr) * 64 + lc;
    int tx = tid & 15, ty = tid >> 4;
    float acc[8][8];
#pragma unroll
    for (int i = 0; i < 8; i++)
#pragma unroll
        for (int j = 0; j < 8; j++) acc[i][j] = 0.0f;

#pragma unroll
    for (int k0 = 0; k0 < 64; k0 += 8) {
        float4 av = *(const float4*)(Ap + k0);
        float4 bv = *(const float4*)(Bp + k0);
        Qs[lc + 0][lr] = av.x; Qs[lc + 1][lr] = av.y;
        Qs[lc + 2][lr] = av.z; Qs[lc + 3][lr] = av.w;
        Ks[lc + 0][lr] = bv.x; Ks[lc + 1][lr] = bv.y;
        Ks[lc + 2][lr] = bv.z; Ks[lc + 3][lr] = bv.w;
        __syncthreads();
#pragma unroll
        for (int k = 0; k < 8; k++) {
            float4 a0 = *(const float4*)&Qs[k][ty * 8];
            float4 a1 = *(const float4*)&Qs[k][ty * 8 + 4];
            float4 b0 = *(const float4*)&Ks[k][tx * 8];
            float4 b1 = *(const float4*)&Ks[k][tx * 8 + 4];
            float a[8] = {a0.x, a0.y, a0.z, a0.w, a1.x, a1.y, a1.z, a1.w};
            float bb[8] = {b0.x, b0.y, b0.z, b0.w, b1.x, b1.y, b1.z, b1.w};
#pragma unroll
            for (int i = 0; i < 8; i++)
#pragma unroll
                for (int j = 0; j < 8; j++) acc[i][j] += a[i] * bb[j];
        }
        __syncthreads();
    }
    float* Cb = g_S + (size_t)bh * 1024 * 1024;
    int crow = blockIdx.y * 128 + ty * 8;
    int ccol = blockIdx.x * 128 + tx * 8;
#pragma unroll
    for (int i = 0; i < 8; i++) {
        *(float4*)(Cb + (size_t)(crow + i) * 1024 + ccol) =
            make_float4(acc[i][0], acc[i][1], acc[i][2], acc[i][3]);
        *(float4*)(Cb + (size_t)(crow + i) * 1024 + ccol + 4) =
            make_float4(acc[i][4], acc[i][5], acc[i][6], acc[i][7]);
    }
}

// ------------------------------ softmax rows --------------------------------
__global__ void k_softmax() {
    __shared__ float red[32];
    float* p = g_S + (size_t)blockIdx.x * 1024;
    int tid = threadIdx.x;
    float4 v = ((float4*)p)[tid];
    float mx = blk_max(fmaxf(fmaxf(v.x, v.y), fmaxf(v.z, v.w)), red);
    v.x = expf(v.x - mx); v.y = expf(v.y - mx);
    v.z = expf(v.z - mx); v.w = expf(v.w - mx);
    float s = blk_sum(v.x + v.y + v.z + v.w, red);
    float inv = 1.0f / s;
    v.x *= inv; v.y *= inv; v.z *= inv; v.w *= inv;
    ((float4*)p)[tid] = v;
}

// ------------------------------ attn @ V : batched NN (N=64) ----------------
__global__ void __launch_bounds__(256, 2)
k_av(const float* __restrict__ V, float* __restrict__ O) {
    __shared__ float Ps[16][128];
    __shared__ float Vs[16][64];
    int bh = blockIdx.z;
    const float* Pb = g_S + (size_t)bh * 1024 * 1024;
    const float* Vb = V + (size_t)bh * 1024 * 64;
    int tid = threadIdx.x;
    int pr = tid >> 1, pc = (tid & 1) << 3;
    int vr = tid >> 4, vc = (tid & 15) << 2;
    int tx = tid & 15, ty = tid >> 4;
    float acc[8][4];
#pragma unroll
    for (int i = 0; i < 8; i++)
#pragma unroll
        for (int j = 0; j < 4; j++) acc[i][j] = 0.0f;

    const float* Prow = Pb + (size_t)(blockIdx.x * 128 + pr) * 1024 + pc;
    for (int k0 = 0; k0 < 1024; k0 += 16) {
        float4 p0 = *(const float4*)(Prow + k0);
        float4 p1 = *(const float4*)(Prow + k0 + 4);
        float4 vv = *(const float4*)(Vb + (size_t)(k0 + vr) * 64 + vc);
        Ps[pc + 0][pr] = p0.x; Ps[pc + 1][pr] = p0.y;
        Ps[pc + 2][pr] = p0.z; Ps[pc + 3][pr] = p0.w;
        Ps[pc + 4][pr] = p1.x; Ps[pc + 5][pr] = p1.y;
        Ps[pc + 6][pr] = p1.z; Ps[pc + 7][pr] = p1.w;
        *(float4*)&Vs[vr][vc] = vv;
        __syncthreads();
#pragma unroll
        for (int k = 0; k < 16; k++) {
            float4 a0 = *(const float4*)&Ps[k][ty * 8];
            float4 a1 = *(const float4*)&Ps[k][ty * 8 + 4];
            float4 b = *(const float4*)&Vs[k][tx * 4];
            float a[8] = {a0.x, a0.y, a0.z, a0.w, a1.x, a1.y, a1.z, a1.w};
            float bb[4] = {b.x, b.y, b.z, b.w};
#pragma unroll
            for (int i = 0; i < 8; i++)
#pragma unroll
                for (int j = 0; j < 4; j++) acc[i][j] += a[i] * bb[j];
        }
        __syncthreads();
    }
    int crow = blockIdx.x * 128 + ty * 8;
    int ccol = tx * 4;
#pragma unroll
    for (int i = 0; i < 8; i++) {
        *(float4*)(O + (size_t)bh * 1024 * 64 + (size_t)(crow + i) * 64 + ccol) =
            make_float4(acc[i][0], acc[i][1], acc[i][2], acc[i][3]);
    }
}

// ------------------------------ merge heads --------------------------------
// U = gel(full) * concat_h( Ot_h * gel(head) * invr )
__global__ void k_merge(const float* __restrict__ Ot, float* __restrict__ U, float invr) {
    __shared__ float red[32];
    int row = blockIdx.x;
    int b = row >> 10, s = row & 1023;
    int tid = threadIdx.x;
    int h = tid >> 4, dd = (tid & 15) << 2;
    float4 v = ((const float4*)(Ot + (((size_t)(b * 16 + h)) * 1024 + s) * 64 + dd))[0];
    float hs = gel_scale(grp16_sum(dot4(v, v))) * invr;
    float t0 = v.x * hs, t1 = v.y * hs, t2 = v.z * hs, t3 = v.w * hs;
    float fs = gel_scale(blk_sum(t0 * t0 + t1 * t1 + t2 * t2 + t3 * t3, red));
    ((float4*)(U + (size_t)row * 1024))[tid] =
        make_float4(t0 * fs, t1 * fs, t2 * fs, t3 * fs);
}

// ------------------------------ post-attn: mobius add + FFN pre -------------
__global__ void k_post_attn(const float* __restrict__ x, const float* __restrict__ Yo,
                            float* __restrict__ Xn, float* __restrict__ U2) {
    __shared__ float red[32];
    int row = blockIdx.x;
    int b = row >> 10;
    int tid = threadIdx.x;
    const float* ab = g_ada + b * 6144;
    float4 yv = ((const float4*)(Yo + (size_t)row * 1024))[tid];
    float sl = gel_scale(blk_sum(dot4(yv, yv), red));        // logmap0(expmap0(y_o))
    float4 gm = ((const float4*)(ab + 2048))[tid];           // g_msa
    float a0 = gm.x * yv.x * sl, a1 = gm.y * yv.y * sl;
    float a2 = gm.z * yv.z * sl, a3 = gm.w * yv.w * sl;
    float na2 = blk_sum(a0 * a0 + a1 * a1 + a2 * a2 + a3 * a3, red);
    float se = gexp_scale(na2);
    float y0 = a0 * se, y1 = a1 * se, y2c = a2 * se, y3 = a3 * se;
    float4 xv = ((const float4*)(x + (size_t)row * 1024))[tid];
    float x2 = blk_sum(dot4(xv, xv), red);
    float y2 = blk_sum(y0 * y0 + y1 * y1 + y2c * y2c + y3 * y3, red);
    float xy = blk_sum(xv.x * y0 + xv.y * y1 + xv.z * y2c + xv.w * y3, red);
    float den = fmaxf(1.0f + 2.0f * xy + x2 * y2, EPSF);
    float cx = (1.0f + 2.0f * xy + y2) / den;
    float cy = (1.0f - x2) / den;
    float n0 = cx * xv.x + cy * y0, n1 = cx * xv.y + cy * y1;
    float n2 = cx * xv.z + cy * y2c, n3 = cx * xv.w + cy * y3;
    ((float4*)(Xn + (size_t)row * 1024))[tid] = make_float4(n0, n1, n2, n3);
    // FFN pre: gel( LN(logmap0(xn)) * (1+sc_mlp) + sh_mlp )
    float ls = glog_scale(blk_sum(n0 * n0 + n1 * n1 + n2 * n2 + n3 * n3, red));
    float t0 = n0 * ls, t1 = n1 * ls, t2 = n2 * ls, t3 = n3 * ls;
    float m = blk_sum(t0 + t1 + t2 + t3, red) * (1.0f / 1024.0f);
    float d0 = t0 - m, d1 = t1 - m, d2 = t2 - m, d3 = t3 - m;
    float var = blk_sum(d0 * d0 + d1 * d1 + d2 * d2 + d3 * d3, red) * (1.0f / 1024.0f);
    float inv = rsqrtf(var + 1e-6f);
    float4 shp = ((const float4*)(ab + 3072))[tid];   // sh_mlp
    float4 scp = ((const float4*)(ab + 4096))[tid];   // sc_mlp
    float m0 = d0 * inv * (1.0f + scp.x) + shp.x;
    float m1 = d1 * inv * (1.0f + scp.y) + shp.y;
    float m2 = d2 * inv * (1.0f + scp.z) + shp.z;
    float m3 = d3 * inv * (1.0f + scp.w) + shp.w;
    float gs = gel_scale(blk_sum(m0 * m0 + m1 * m1 + m2 * m2 + m3 * m3, red));
    ((float4*)(U2 + (size_t)row * 1024))[tid] =
        make_float4(m0 * gs, m1 * gs, m2 * gs, m3 * gs);
}

// ------------------------------ FF renorm (rows of 4096) --------------------
__global__ void k_renorm_ff(float* __restrict__ Y1) {
    __shared__ float red[32];
    int row = blockIdx.x;
    int tid = threadIdx.x;
    float4* p = (float4*)(Y1 + (size_t)row * 4096);
    float4 v0 = p[tid], v1 = p[tid + 256], v2 = p[tid + 512], v3 = p[tid + 768];
    float s2 = dot4(v0, v0) + dot4(v1, v1) + dot4(v2, v2) + dot4(v3, v3);
    float s = gel_scale(blk_sum(s2, red));
    v0.x *= s; v0.y *= s; v0.z *= s; v0.w *= s;
    v1.x *= s; v1.y *= s; v1.z *= s; v1.w *= s;
    v2.x *= s; v2.y *= s; v2.z *= s; v2.w *= s;
    v3.x *= s; v3.y *= s; v3.z *= s; v3.w *= s;
    p[tid] = v0; p[tid + 256] = v1; p[tid + 512] = v2; p[tid + 768] = v3;
}

// ------------------------------ final: FFN mobius add -----------------------
__global__ void k_final(const float* __restrict__ Xn, const float* __restrict__ Y2,
                        float* __restrict__ out) {
    __shared__ float red[32];
    int row = blockIdx.x;
    int b = row >> 10;
    int tid = threadIdx.x;
    const float* ab = g_ada + b * 6144;
    float4 yv = ((const float4*)(Y2 + (size_t)row * 1024))[tid];
    float sl = gel_scale(blk_sum(dot4(yv, yv), red));
    float4 gm = ((const float4*)(ab + 5120))[tid];   // g_mlp
    float a0 = gm.x * yv.x * sl, a1 = gm.y * yv.y * sl;
    float a2 = gm.z * yv.z * sl, a3 = gm.w * yv.w * sl;
    float na2 = blk_sum(a0 * a0 + a1 * a1 + a2 * a2 + a3 * a3, red);
    float se = gexp_scale(na2);
    float y0 = a0 * se, y1 = a1 * se, y2c = a2 * se, y3 = a3 * se;
    float4 xv = ((const float4*)(Xn + (size_t)row * 1024))[tid];
    float x2 = blk_sum(dot4(xv, xv), red);
    float y2 = blk_sum(y0 * y0 + y1 * y1 + y2c * y2c + y3 * y3, red);
    float xy = blk_sum(xv.x * y0 + xv.y * y1 + xv.z * y2c + xv.w * y3, red);
    float den = fmaxf(1.0f + 2.0f * xy + x2 * y2, EPSF);
    float cx = (1.0f + 2.0f * xy + y2) / den;
    float cy = (1.0f - x2) / den;
    ((float4*)(out + (size_t)row * 1024))[tid] =
        make_float4(cx * xv.x + cy * y0, cx * xv.y + cy * y1,
                    cx * xv.z + cy * y2c, cx * xv.w + cy * y3);
}

// ------------------------------ launcher -----------------------------------
extern "C" void kernel_launch(void* const* d_in, const int* in_sizes, int n_in,
                              void* d_out, int out_size) {
    const float* x     = (const float*)d_in[0];
    const float* t_emb = (const float*)d_in[1];
    const float* w_q   = (const float*)d_in[2];
    const float* b_q   = (const float*)d_in[3];
    const float* w_k   = (const float*)d_in[4];
    const float* b_k   = (const float*)d_in[5];
    const float* w_v   = (const float*)d_in[6];
    const float* b_v   = (const float*)d_in[7];
    const float* w_o   = (const float*)d_in[8];
    const float* b_o   = (const float*)d_in[9];
    const float* w_f1  = (const float*)d_in[10];
    const float* b_f1  = (const float*)d_in[11];
    const float* w_f2  = (const float*)d_in[12];
    const float* b_f2  = (const float*)d_in[13];
    const float* w_ada = (const float*)d_in[14];
    const float* b_ada = (const float*)d_in[15];
    float* out = (float*)d_out;

    // beta(D/2, 1/2) ratios, computed in double exactly like the reference
    double bn = exp(lgamma(512.0) + lgamma(0.5) - lgamma(512.5));
    double bh = exp(lgamma(32.0) + lgamma(0.5) - lgamma(32.5));
    float rscale = (float)(bh / bn);   // BETA_H / BETA_N
    float invr   = (float)(bn / bh);   // BETA_N / BETA_H

    float *pU, *pY, *pQt, *pKt, *pVt, *pOt, *pXn, *pY1;
    cudaGetSymbolAddress((void**)&pU,  g_U);
    cudaGetSymbolAddress((void**)&pY,  g_Y);
    cudaGetSymbolAddress((void**)&pQt, g_Qt);
    cudaGetSymbolAddress((void**)&pKt, g_Kt);
    cudaGetSymbolAddress((void**)&pVt, g_Vt);
    cudaGetSymbolAddress((void**)&pOt, g_Ot);
    cudaGetSymbolAddress((void**)&pXn, g_Xn);
    cudaGetSymbolAddress((void**)&pY1, g_Y1);

    // ada params
    k_ada<<<dim3(24, 4), 256>>>(t_emb, w_ada, b_ada);
    // attention pre
    k_pre<<<4096, 256>>>(x, pU);
    // Q, K, V projections + head split (q pre-scaled by 1/sqrt(HD)=0.125)
    sgemm_nn<<<dim3(8, 32), 256>>>(pU, w_q, b_q, pY, 4096, 1024, 1024);
    k_split<<<4096, 256>>>(pY, pQt, rscale, 0.125f);
    sgemm_nn<<<dim3(8, 32), 256>>>(pU, w_k, b_k, pY, 4096, 1024, 1024);
    k_split<<<4096, 256>>>(pY, pKt, rscale, 1.0f);
    sgemm_nn<<<dim3(8, 32), 256>>>(pU, w_v, b_v, pY, 4096, 1024, 1024);
    k_split<<<4096, 256>>>(pY, pVt, rscale, 1.0f);
    // attention
    k_scores<<<dim3(8, 8, 64), 256>>>(pQt, pKt);
    k_softmax<<<65536, 256>>>();
    k_av<<<dim3(8, 1, 64), 256>>>(pVt, pOt);
    // merge heads + O projection
    k_merge<<<4096, 256>>>(pOt, pU, invr);
    sgemm_nn<<<dim3(8, 32), 256>>>(pU, w_o, b_o, pY, 4096, 1024, 1024);
    // mobius residual + FFN pre
    k_post_attn<<<4096, 256>>>(x, pY, pXn, pU);
    // FFN
    sgemm_nn<<<dim3(32, 32), 256>>>(pU, w_f1, b_f1, pY1, 4096, 4096, 1024);
    k_renorm_ff<<<4096, 256>>>(pY1);
    sgemm_nn<<<dim3(8, 32), 256>>>(pY1, w_f2, b_f2, pY, 4096, 1024, 4096);
    // final mobius residual
    k_final<<<4096, 256>>>(pXn, pY, out);
}